// round 1
// baseline (speedup 1.0000x reference)
#include <cuda_runtime.h>
#include <cstdint>

#define COLS 16384
#define THREADS 256
#define V4_PER_THREAD (COLS / THREADS / 4)   // 16 float4 per thread

// Order-preserving float -> uint transform (ascending order)
__device__ __forceinline__ unsigned key_of(float f) {
    unsigned u = __float_as_uint(f);
    return u ^ ((u >> 31) ? 0xFFFFFFFFu : 0x80000000u);
}

extern __shared__ unsigned char smem_raw[];

__global__ void __launch_bounds__(THREADS, 3)
topk_threshold_kernel(const float* __restrict__ x,
                      float* __restrict__ out,
                      const int* __restrict__ kptr)
{
    float*    row  = (float*)smem_raw;                         // 65536 B
    unsigned* hist = (unsigned*)(smem_raw + 65536);            // 8192 B (2048 bins max)
    unsigned* ssum = (unsigned*)(smem_raw + 65536 + 8192);     // 1024 B
    __shared__ unsigned sh_prefix;
    __shared__ unsigned sh_krem;
    __shared__ unsigned sh_group;

    const int tid = threadIdx.x;
    const size_t row_off = (size_t)blockIdx.x * COLS;
    const float4* __restrict__ xin  = (const float4*)(x + row_off);
    float4* __restrict__       oout = (float4*)(out + row_off);
    float4* srow = (float4*)row;

    // ---- Phase 1: load the full row into shared memory (the ONLY global read) ----
    #pragma unroll
    for (int i = 0; i < V4_PER_THREAD; i++) {
        srow[tid + i * THREADS] = xin[tid + i * THREADS];
    }

    const int k = kptr ? __ldg(kptr) : 64;
    if (tid == 0) { sh_krem = (unsigned)k; sh_prefix = 0u; }
    __syncthreads();

    // ---- Phase 2: exact 32-bit radix select (3 passes: 11 + 11 + 10 bits) ----
    unsigned prefix = 0;
    int prefix_len = 0;
    const int pass_bits[3]  = {11, 11, 10};
    const int pass_shift[3] = {21, 10, 0};

    #pragma unroll
    for (int pass = 0; pass < 3; pass++) {
        const int nbins = 1 << pass_bits[pass];
        const int gsz   = nbins / THREADS;   // 8, 8, 4 bins per thread

        for (int b = tid; b < nbins; b += THREADS) hist[b] = 0u;
        __syncthreads();

        // histogram of elements matching current prefix
        #pragma unroll
        for (int i = 0; i < V4_PER_THREAD; i++) {
            float4 v = srow[tid + i * THREADS];
            #pragma unroll
            for (int j = 0; j < 4; j++) {
                float f = ((const float*)&v)[j];
                unsigned key = key_of(f);
                bool match = (pass == 0) || ((key >> (32 - prefix_len)) == prefix);
                if (match) {
                    unsigned bin = (key >> pass_shift[pass]) & (unsigned)(nbins - 1);
                    atomicAdd(&hist[bin], 1u);
                }
            }
        }
        __syncthreads();

        // per-thread group sum (bins [tid*gsz, tid*gsz+gsz))
        unsigned s = 0;
        #pragma unroll 8
        for (int j = 0; j < gsz; j++) s += hist[tid * gsz + j];
        ssum[tid] = s;
        __syncthreads();

        // block-wide suffix sum over the 256 group sums
        #pragma unroll
        for (int off = 1; off < THREADS; off <<= 1) {
            unsigned v = (tid + off < THREADS) ? ssum[tid + off] : 0u;
            __syncthreads();
            ssum[tid] += v;
            __syncthreads();
        }

        // find the group where the cumulative-from-top count crosses krem
        const unsigned krem = sh_krem;
        unsigned me   = ssum[tid];
        unsigned next = (tid + 1 < THREADS) ? ssum[tid + 1] : 0u;
        if (me >= krem && next < krem) sh_group = (unsigned)tid;
        __syncthreads();

        if (tid == 0) {
            int g = (int)sh_group;
            unsigned above = (g + 1 < THREADS) ? ssum[g + 1] : 0u;
            int bin = 0;
            for (int b = gsz - 1; b >= 0; b--) {
                unsigned c = hist[g * gsz + b];
                if (above + c >= krem) { bin = g * gsz + b; break; }
                above += c;
            }
            sh_krem   = krem - above;
            sh_prefix = (sh_prefix << pass_bits[pass]) | (unsigned)bin;
        }
        __syncthreads();
        prefix = sh_prefix;
        prefix_len += pass_bits[pass];
    }

    const unsigned tkey = prefix;   // exact 32-bit key of the k-th largest value

    // ---- Phase 3: stream output from smem (the ONLY global write) ----
    #pragma unroll
    for (int i = 0; i < V4_PER_THREAD; i++) {
        float4 v = srow[tid + i * THREADS];
        float4 o;
        #pragma unroll
        for (int j = 0; j < 4; j++) {
            float f = ((const float*)&v)[j];
            ((float*)&o)[j] = (key_of(f) >= tkey) ? f : 0.0f;
        }
        oout[tid + i * THREADS] = o;
    }
}

extern "C" void kernel_launch(void* const* d_in, const int* in_sizes, int n_in,
                              void* d_out, int out_size) {
    const float* x   = (const float*)d_in[0];
    const int* kptr  = (n_in > 1) ? (const int*)d_in[1] : nullptr;
    const int rows   = in_sizes[0] / COLS;

    const size_t smem = 65536 + 8192 + 1024;   // row + hist + scan scratch
    cudaFuncSetAttribute(topk_threshold_kernel,
                         cudaFuncAttributeMaxDynamicSharedMemorySize, (int)smem);
    topk_threshold_kernel<<<rows, THREADS, smem>>>(x, (float*)d_out, kptr);
}

// round 2
// speedup vs baseline: 1.1189x; 1.1189x over previous
#include <cuda_runtime.h>
#include <cstdint>

#define COLS 16384
#define THREADS 256
#define NBINS 2048            // 11-bit first pass
#define CAP   2048            // candidate buffer capacity (reuses hist region)
#define V4_PER_THREAD (COLS / THREADS / 4)   // 16

// Order-preserving float -> uint transform (ascending)
__device__ __forceinline__ unsigned key_of(unsigned u) {
    return u ^ ((u >> 31) ? 0xFFFFFFFFu : 0x80000000u);
}
// Inverse transform
__device__ __forceinline__ float val_of(unsigned k) {
    unsigned u = (k & 0x80000000u) ? (k ^ 0x80000000u) : ~k;
    return __uint_as_float(u);
}

extern __shared__ unsigned char smem_raw[];

__global__ void __launch_bounds__(THREADS, 3)
topk_threshold_kernel(const float* __restrict__ x,
                      float* __restrict__ out,
                      const int* __restrict__ kptr)
{
    unsigned* keys = (unsigned*)smem_raw;                   // 65536 B (16384 keys)
    unsigned* hist = (unsigned*)(smem_raw + 65536);         // 8192 B (2048 bins)
    unsigned* cand = hist;                                  // reused after bin select
    __shared__ unsigned wsum[8];
    __shared__ unsigned sh_bin, sh_krem, sh_bincnt, sh_cnt, sh_tkey, sh_c;

    const int tid  = threadIdx.x;
    const int lane = tid & 31;
    const int wid  = tid >> 5;
    const size_t row_off = (size_t)blockIdx.x * COLS;
    const uint4* __restrict__ xin = (const uint4*)(x + row_off);
    float4* __restrict__ oout     = (float4*)(out + row_off);
    uint4* skeys = (uint4*)keys;

    // zero histogram
    #pragma unroll
    for (int b = tid; b < NBINS; b += THREADS) hist[b] = 0u;
    const int k = kptr ? __ldg(kptr) : 64;
    __syncthreads();

    // ---- Phase 1: load row, transform to keys, store keys to smem, histogram (merged) ----
    #pragma unroll
    for (int i = 0; i < V4_PER_THREAD; i++) {
        uint4 v = __ldcs(&xin[tid + i * THREADS]);
        uint4 kk;
        kk.x = key_of(v.x); kk.y = key_of(v.y);
        kk.z = key_of(v.z); kk.w = key_of(v.w);
        skeys[tid + i * THREADS] = kk;
        atomicAdd(&hist[kk.x >> 21], 1u);
        atomicAdd(&hist[kk.y >> 21], 1u);
        atomicAdd(&hist[kk.z >> 21], 1u);
        atomicAdd(&hist[kk.w >> 21], 1u);
    }
    __syncthreads();

    // ---- Phase 2: find the bin containing the k-th largest ----
    // each thread owns 8 consecutive bins
    unsigned gs = 0;
    #pragma unroll
    for (int j = 0; j < 8; j++) gs += hist[tid * 8 + j];
    // intra-warp inclusive suffix sum (toward higher lanes = higher bins)
    unsigned s = gs;
    #pragma unroll
    for (int off = 1; off < 32; off <<= 1) {
        unsigned v = __shfl_down_sync(0xFFFFFFFFu, s, off);
        if (lane + off < 32) s += v;
    }
    if (lane == 0) wsum[wid] = s;   // warp total
    __syncthreads();
    unsigned woff = 0;
    #pragma unroll
    for (int w = 0; w < 8; w++) woff += (w > wid) ? wsum[w] : 0u;
    unsigned ssum = s + woff;       // suffix sum from this group upward

    const unsigned krem0 = (unsigned)k;
    if (ssum >= krem0 && (ssum - gs) < krem0) {
        unsigned above = ssum - gs;
        int b = 0;
        #pragma unroll
        for (int bb = 7; bb >= 0; bb--) {
            unsigned c = hist[tid * 8 + bb];
            if (above + c >= krem0) { b = bb; break; }
            above += c;
        }
        sh_bin    = (unsigned)(tid * 8 + b);
        sh_krem   = krem0 - above;       // rank within the tie bin
        sh_bincnt = hist[tid * 8 + b];
        sh_cnt    = 0u;
    }
    __syncthreads();

    const unsigned binp   = sh_bin;
    const unsigned krem1  = sh_krem;
    const unsigned bincnt = sh_bincnt;

    if (bincnt <= CAP) {
        // ---- Phase 3a: compact tie-bin candidates (hist region now reusable) ----
        #pragma unroll
        for (int i = 0; i < V4_PER_THREAD; i++) {
            uint4 kk = skeys[tid + i * THREADS];
            #pragma unroll
            for (int j = 0; j < 4; j++) {
                unsigned ky = ((const unsigned*)&kk)[j];
                if ((ky >> 21) == binp) {
                    unsigned p = atomicAdd(&sh_cnt, 1u);
                    cand[p] = ky;
                }
            }
        }
        __syncthreads();

        // ---- Phase 3b: warp 0 refines remaining 21 bits over the small candidate set ----
        if (wid == 0) {
            const int n = (int)sh_cnt;
            unsigned krem = krem1;
            unsigned cur  = 0u;
            for (int bit = 20; bit >= 0; bit--) {
                unsigned want = (cur << 1) | 1u;
                unsigned mask = (1u << (21 - bit)) - 1u;
                unsigned cnt = 0;
                for (int i = lane; i < n; i += 32)
                    cnt += (((cand[i] >> bit) & mask) == want);
                cnt = __reduce_add_sync(0xFFFFFFFFu, cnt);
                if (cnt >= krem) cur = want;
                else { cur = want - 1u; krem -= cnt; }
            }
            if (lane == 0) sh_tkey = (binp << 21) | cur;
        }
        __syncthreads();
    } else {
        // ---- Fallback (never taken for Gaussian data, kept for correctness):
        // bitwise select over the full row for the remaining 21 bits.
        unsigned krem = krem1;
        unsigned cur  = 0u;
        for (int bit = 20; bit >= 0; bit--) {
            if (tid == 0) sh_c = 0u;
            __syncthreads();
            unsigned want  = (cur << 1) | 1u;
            unsigned fullw = (binp << (21 - bit)) | want;
            unsigned local = 0;
            #pragma unroll
            for (int i = 0; i < V4_PER_THREAD; i++) {
                uint4 kk = skeys[tid + i * THREADS];
                local += ((kk.x >> bit) == fullw);
                local += ((kk.y >> bit) == fullw);
                local += ((kk.z >> bit) == fullw);
                local += ((kk.w >> bit) == fullw);
            }
            local = __reduce_add_sync(0xFFFFFFFFu, local);
            if (lane == 0) atomicAdd(&sh_c, local);
            __syncthreads();
            unsigned cnt = sh_c;
            if (cnt >= krem) cur = want;
            else { cur = want - 1u; krem -= cnt; }
            __syncthreads();
        }
        if (tid == 0) sh_tkey = (binp << 21) | cur;
        __syncthreads();
    }

    const unsigned tkey = sh_tkey;

    // ---- Phase 4: stream output from smem keys ----
    #pragma unroll
    for (int i = 0; i < V4_PER_THREAD; i++) {
        uint4 kk = skeys[tid + i * THREADS];
        float4 o;
        o.x = (kk.x >= tkey) ? val_of(kk.x) : 0.0f;
        o.y = (kk.y >= tkey) ? val_of(kk.y) : 0.0f;
        o.z = (kk.z >= tkey) ? val_of(kk.z) : 0.0f;
        o.w = (kk.w >= tkey) ? val_of(kk.w) : 0.0f;
        __stcs(&oout[tid + i * THREADS], o);
    }
}

extern "C" void kernel_launch(void* const* d_in, const int* in_sizes, int n_in,
                              void* d_out, int out_size) {
    const float* x  = (const float*)d_in[0];
    const int* kptr = (n_in > 1) ? (const int*)d_in[1] : nullptr;
    const int rows  = in_sizes[0] / COLS;

    const size_t smem = 65536 + 8192;   // keys + hist/cand
    cudaFuncSetAttribute(topk_threshold_kernel,
                         cudaFuncAttributeMaxDynamicSharedMemorySize, (int)smem);
    topk_threshold_kernel<<<rows, THREADS, smem>>>(x, (float*)d_out, kptr);
}

// round 3
// speedup vs baseline: 1.4486x; 1.2947x over previous
#include <cuda_runtime.h>
#include <cstdint>

#define COLS    16384
#define THREADS 512
#define V4      8                 // float4 per thread (32 elements)
#define NBINS   2048              // 11-bit first pass
#define CAP     2048
#define REGCAND 256               // register-refine path limit (8 per lane)

// Order-preserving float -> uint transform (ascending)
__device__ __forceinline__ unsigned key_of(unsigned u) {
    return u ^ ((u >> 31) ? 0xFFFFFFFFu : 0x80000000u);
}
__device__ __forceinline__ float val_of(unsigned k) {
    unsigned u = (k & 0x80000000u) ? (k ^ 0x80000000u) : ~k;
    return __uint_as_float(u);
}

__global__ void __launch_bounds__(THREADS, 2)
topk_threshold_kernel(const float* __restrict__ x,
                      float* __restrict__ out,
                      const int* __restrict__ kptr)
{
    __shared__ unsigned hist[NBINS];    // 8 KB; reused as candidate buffer
    __shared__ unsigned wsum[16];
    __shared__ unsigned sh_bin, sh_krem, sh_bincnt, sh_cnt, sh_tkey, sh_c;
    unsigned* cand = hist;

    const int tid  = threadIdx.x;
    const int lane = tid & 31;
    const int wid  = tid >> 5;
    const size_t row_off = (size_t)blockIdx.x * COLS;
    const uint4* __restrict__ xin = (const uint4*)(x + row_off);
    float4* __restrict__ oout     = (float4*)(out + row_off);

    #pragma unroll
    for (int b = tid; b < NBINS; b += THREADS) hist[b] = 0u;
    const unsigned k = kptr ? (unsigned)__ldg(kptr) : 64u;
    __syncthreads();

    // ---- Phase 1: load row into REGISTERS (keys), histogram top 11 bits ----
    uint4 kk[V4];
    #pragma unroll
    for (int i = 0; i < V4; i++) {
        uint4 v = __ldcs(&xin[tid + i * THREADS]);
        kk[i].x = key_of(v.x); kk[i].y = key_of(v.y);
        kk[i].z = key_of(v.z); kk[i].w = key_of(v.w);
        atomicAdd(&hist[kk[i].x >> 21], 1u);
        atomicAdd(&hist[kk[i].y >> 21], 1u);
        atomicAdd(&hist[kk[i].z >> 21], 1u);
        atomicAdd(&hist[kk[i].w >> 21], 1u);
    }
    __syncthreads();

    // ---- Phase 2: find bin of the k-th largest (block suffix-sum) ----
    unsigned gs = hist[tid * 4 + 0] + hist[tid * 4 + 1]
                + hist[tid * 4 + 2] + hist[tid * 4 + 3];
    unsigned s = gs;
    #pragma unroll
    for (int off = 1; off < 32; off <<= 1) {
        unsigned v = __shfl_down_sync(0xFFFFFFFFu, s, off);
        if (lane + off < 32) s += v;
    }
    if (lane == 0) wsum[wid] = s;
    __syncthreads();
    unsigned woff = 0;
    #pragma unroll
    for (int w = 0; w < 16; w++) woff += (w > wid) ? wsum[w] : 0u;
    unsigned ssum = s + woff;    // count of elements in bins >= my group

    if (ssum >= k && (ssum - gs) < k) {
        unsigned above = ssum - gs;
        int b = 0;
        #pragma unroll
        for (int bb = 3; bb >= 0; bb--) {
            unsigned c = hist[tid * 4 + bb];
            if (above + c >= k) { b = bb; break; }
            above += c;
        }
        sh_bin    = (unsigned)(tid * 4 + b);
        sh_krem   = k - above;
        sh_bincnt = hist[tid * 4 + b];
        sh_cnt    = 0u;
    }
    __syncthreads();

    const unsigned binp   = sh_bin;
    const unsigned krem1  = sh_krem;
    const unsigned bincnt = sh_bincnt;

    if (bincnt <= CAP) {
        // ---- Phase 3a: compact tie-bin candidates from registers ----
        #pragma unroll
        for (int i = 0; i < V4; i++) {
            #pragma unroll
            for (int j = 0; j < 4; j++) {
                unsigned ky = ((const unsigned*)&kk[i])[j];
                if ((ky >> 21) == binp) {
                    unsigned p = atomicAdd(&sh_cnt, 1u);
                    cand[p] = ky;
                }
            }
        }
        __syncthreads();

        // ---- Phase 3b: warp 0 refines the remaining 21 bits ----
        if (wid == 0) {
            const int n = (int)sh_cnt;
            unsigned krem = krem1;
            unsigned cur  = 0u;
            if (n <= REGCAND) {
                // cache candidates in registers once (pad: low 21 bits = 0, never matches)
                unsigned c[8];
                #pragma unroll
                for (int j = 0; j < 8; j++)
                    c[j] = (lane + 32 * j < n) ? cand[lane + 32 * j] : 0u;
                for (int bit = 20; bit >= 0; bit--) {
                    unsigned want = (cur << 1) | 1u;
                    unsigned mask = (1u << (21 - bit)) - 1u;
                    unsigned cnt = 0;
                    #pragma unroll
                    for (int j = 0; j < 8; j++)
                        cnt += (((c[j] >> bit) & mask) == want);
                    cnt = __reduce_add_sync(0xFFFFFFFFu, cnt);
                    if (cnt >= krem) cur = want;
                    else { cur = want - 1u; krem -= cnt; }
                }
            } else {
                for (int bit = 20; bit >= 0; bit--) {
                    unsigned want = (cur << 1) | 1u;
                    unsigned mask = (1u << (21 - bit)) - 1u;
                    unsigned cnt = 0;
                    for (int i = lane; i < n; i += 32)
                        cnt += (((cand[i] >> bit) & mask) == want);
                    cnt = __reduce_add_sync(0xFFFFFFFFu, cnt);
                    if (cnt >= krem) cur = want;
                    else { cur = want - 1u; krem -= cnt; }
                }
            }
            if (lane == 0) sh_tkey = (binp << 21) | cur;
        }
        __syncthreads();
    } else {
        // ---- Fallback (pathological tie bin): block-wide bitwise select over registers ----
        unsigned krem = krem1;
        unsigned cur  = 0u;
        for (int bit = 20; bit >= 0; bit--) {
            if (tid == 0) sh_c = 0u;
            __syncthreads();
            unsigned want  = (cur << 1) | 1u;
            unsigned fullw = (binp << (21 - bit)) | want;
            unsigned local = 0;
            #pragma unroll
            for (int i = 0; i < V4; i++) {
                local += ((kk[i].x >> bit) == fullw);
                local += ((kk[i].y >> bit) == fullw);
                local += ((kk[i].z >> bit) == fullw);
                local += ((kk[i].w >> bit) == fullw);
            }
            local = __reduce_add_sync(0xFFFFFFFFu, local);
            if (lane == 0) atomicAdd(&sh_c, local);
            __syncthreads();
            unsigned cnt = sh_c;
            if (cnt >= krem) cur = want;
            else { cur = want - 1u; krem -= cnt; }
            __syncthreads();
        }
        if (tid == 0) sh_tkey = (binp << 21) | cur;
        __syncthreads();
    }

    const unsigned tkey = sh_tkey;

    // ---- Phase 4: stream output straight from registers ----
    #pragma unroll
    for (int i = 0; i < V4; i++) {
        float4 o;
        o.x = (kk[i].x >= tkey) ? val_of(kk[i].x) : 0.0f;
        o.y = (kk[i].y >= tkey) ? val_of(kk[i].y) : 0.0f;
        o.z = (kk[i].z >= tkey) ? val_of(kk[i].z) : 0.0f;
        o.w = (kk[i].w >= tkey) ? val_of(kk[i].w) : 0.0f;
        __stcs(&oout[tid + i * THREADS], o);
    }
}

extern "C" void kernel_launch(void* const* d_in, const int* in_sizes, int n_in,
                              void* d_out, int out_size) {
    const float* x  = (const float*)d_in[0];
    const int* kptr = (n_in > 1) ? (const int*)d_in[1] : nullptr;
    const int rows  = in_sizes[0] / COLS;
    topk_threshold_kernel<<<rows, THREADS>>>(x, (float*)d_out, kptr);
}